// round 1
// baseline (speedup 1.0000x reference)
#include <cuda_runtime.h>

#define GV 1024
#define GB 128
#define KORD 5

// ---------------- scratch (device globals; no allocation) ----------------
__device__ float g_fk[(size_t)GB * 960 * GV];    // Chebyshev feature matrix [B, C*K, V] (max CK=960)
__device__ float g_act[(size_t)GB * 192 * GV];   // conv output Y [B, F, V] (max F=192)
__device__ float g_bn_s[192];                    // per-channel scale  g*rsqrt(var+eps)
__device__ float g_bn_t[192];                    // per-channel shift  b - mean*scale
__device__ float g_bn_mean[192];                 // per-channel mean (pass 1)

// 1/sqrt(deg) for deg in {2,3,4}
__device__ __forceinline__ float rsd_of(int i, int j) {
    int deg = (i > 0) + (i < 31) + (j > 0) + (j < 31);
    // deg is 2,3,4
    return (deg == 4) ? 0.5f : (deg == 3 ? 0.57735026918962576f : 0.70710678118654752f);
}

// ---------------- Chebyshev expansion (stencil recursion) ----------------
// in:  [B, C, V] activations (raw conv output of previous layer, or network input)
// out: g_fk[b, c*5+k, v],  k = 0..4
// If apply_bn: x <- relu(x*bn_s[c] + bn_t[c]) on load.
__global__ void cheb_expand(const float* __restrict__ in, int C, int apply_bn) {
    __shared__ float s[GV];
    const int v = threadIdx.x;
    const int c = blockIdx.x;
    const int b = blockIdx.y;
    const int i = v >> 5, j = v & 31;

    float x = in[((size_t)b * C + c) * GV + v];
    if (apply_bn) x = fmaxf(fmaf(x, g_bn_s[c], g_bn_t[c]), 0.0f);

    // L~ = -D^{-1/2} A D^{-1/2} : 4-neighbor stencil weights
    const float rv = rsd_of(i, j);
    const float w_up = (i > 0)  ? rv * rsd_of(i - 1, j) : 0.f;
    const float w_dn = (i < 31) ? rv * rsd_of(i + 1, j) : 0.f;
    const float w_lf = (j > 0)  ? rv * rsd_of(i, j - 1) : 0.f;
    const float w_rt = (j < 31) ? rv * rsd_of(i, j + 1) : 0.f;
    const int up = (i > 0)  ? v - 32 : v;
    const int dn = (i < 31) ? v + 32 : v;
    const int lf = (j > 0)  ? v - 1  : v;
    const int rt = (j < 31) ? v + 1  : v;

    const size_t base = ((size_t)b * (C * KORD) + (size_t)c * KORD) * GV + v;

    // T0
    g_fk[base] = x;
    s[v] = x;
    __syncthreads();
    // T1 = L x
    float t1 = -(w_up * s[up] + w_dn * s[dn] + w_lf * s[lf] + w_rt * s[rt]);
    g_fk[base + GV] = t1;

    float tp = x, tc = t1;
#pragma unroll
    for (int k = 2; k < KORD; k++) {
        __syncthreads();
        s[v] = tc;
        __syncthreads();
        float l = -(w_up * s[up] + w_dn * s[dn] + w_lf * s[lf] + w_rt * s[rt]);
        float tn = fmaf(2.0f, l, -tp);
        g_fk[base + (size_t)k * GV] = tn;
        tp = tc;
        tc = tn;
    }
}

// ---------------- batched GEMM:  Y[b] = W @ Fk[b] ----------------
// W:  [F, CK] row-major, Fk[b]: [CK, V] row-major, Y: [B, F, V]
#define BM 64
#define BN 128
#define BK 16

__global__ __launch_bounds__(256, 2)
void gemm_batched(const float* __restrict__ Wm, int F, int CK) {
    __shared__ float As[BK][BM];
    __shared__ float Bs[BK][BN];

    const int b  = blockIdx.z;
    const int m0 = blockIdx.x * BM;
    const int n0 = blockIdx.y * BN;
    const int t  = threadIdx.x;
    const int tm = t >> 4;        // 0..15 (4 rows each)
    const int tn = t & 15;        // 0..15 (8 cols each)

    const float* FkB = g_fk + (size_t)b * CK * GV;

    float acc[4][8];
#pragma unroll
    for (int ii = 0; ii < 4; ii++)
#pragma unroll
        for (int jj = 0; jj < 8; jj++) acc[ii][jj] = 0.f;

    const int ar  = t >> 2;        // 0..63  (A row)
    const int ac0 = (t & 3) * 4;   // A col group
    const int br  = t >> 4;        // 0..15  (B row)
    const int bc  = (t & 15) * 8;  // B col group

    for (int k0 = 0; k0 < CK; k0 += BK) {
        // load A tile (scalar, guarded: CK may be 15, F may be 96)
#pragma unroll
        for (int e = 0; e < 4; e++) {
            int kk = ac0 + e;
            int kg = k0 + kk, mg = m0 + ar;
            As[kk][ar] = (mg < F && kg < CK) ? Wm[(size_t)mg * CK + kg] : 0.f;
        }
        // load B tile (vectorized, V=1024 rows are 16B aligned)
        {
            int kg = k0 + br;
            if (kg < CK) {
                const float* src = FkB + (size_t)kg * GV + n0 + bc;
                *(float4*)&Bs[br][bc]     = *(const float4*)(src);
                *(float4*)&Bs[br][bc + 4] = *(const float4*)(src + 4);
            } else {
                float4 z = make_float4(0.f, 0.f, 0.f, 0.f);
                *(float4*)&Bs[br][bc]     = z;
                *(float4*)&Bs[br][bc + 4] = z;
            }
        }
        __syncthreads();
#pragma unroll
        for (int kk = 0; kk < BK; kk++) {
            float4 a  = *(const float4*)&As[kk][tm * 4];
            float4 q0 = *(const float4*)&Bs[kk][tn * 8];
            float4 q1 = *(const float4*)&Bs[kk][tn * 8 + 4];
            float av[4] = {a.x, a.y, a.z, a.w};
            float bv[8] = {q0.x, q0.y, q0.z, q0.w, q1.x, q1.y, q1.z, q1.w};
#pragma unroll
            for (int ii = 0; ii < 4; ii++)
#pragma unroll
                for (int jj = 0; jj < 8; jj++)
                    acc[ii][jj] = fmaf(av[ii], bv[jj], acc[ii][jj]);
        }
        __syncthreads();
    }

#pragma unroll
    for (int ii = 0; ii < 4; ii++) {
        int mg = m0 + tm * 4 + ii;
        if (mg < F) {
            float* dst = g_act + ((size_t)b * F + mg) * GV + n0 + tn * 8;
            *(float4*)dst       = make_float4(acc[ii][0], acc[ii][1], acc[ii][2], acc[ii][3]);
            *(float4*)(dst + 4) = make_float4(acc[ii][4], acc[ii][5], acc[ii][6], acc[ii][7]);
        }
    }
}

// ---------------- BN statistics (two-pass for numerical safety) ----------------
__global__ void bn_mean(int F) {
    __shared__ float red[256];
    const int f = blockIdx.x;
    float sum = 0.f;
    for (int idx = threadIdx.x; idx < GB * GV; idx += 256) {
        int b = idx >> 10, v = idx & (GV - 1);
        sum += g_act[((size_t)b * F + f) * GV + v];
    }
    red[threadIdx.x] = sum;
    __syncthreads();
    for (int s = 128; s > 0; s >>= 1) {
        if (threadIdx.x < s) red[threadIdx.x] += red[threadIdx.x + s];
        __syncthreads();
    }
    if (threadIdx.x == 0) g_bn_mean[f] = red[0] / (float)(GB * GV);
}

__global__ void bn_var(int F, const float* __restrict__ gamma, const float* __restrict__ beta) {
    __shared__ float red[256];
    const int f = blockIdx.x;
    const float m = g_bn_mean[f];
    float sq = 0.f;
    for (int idx = threadIdx.x; idx < GB * GV; idx += 256) {
        int b = idx >> 10, v = idx & (GV - 1);
        float d = g_act[((size_t)b * F + f) * GV + v] - m;
        sq = fmaf(d, d, sq);
    }
    red[threadIdx.x] = sq;
    __syncthreads();
    for (int s = 128; s > 0; s >>= 1) {
        if (threadIdx.x < s) red[threadIdx.x] += red[threadIdx.x + s];
        __syncthreads();
    }
    if (threadIdx.x == 0) {
        float var = red[0] / (float)(GB * GV);
        float sc  = gamma[f] * rsqrtf(var + 1e-5f);
        g_bn_s[f] = sc;
        g_bn_t[f] = beta[f] - m * sc;
    }
}

// ---------------- classifier: out[b,o] = sum_f relu(bn(Y6))[b,f] * clf_w[o,f] + clf_b[o] ----------------
__global__ void classifier(const float* __restrict__ cw, const float* __restrict__ cb,
                           float* __restrict__ out) {
    const int b0   = blockIdx.x * 4;
    const int lane = threadIdx.x & 31;
    const int warp = threadIdx.x >> 5;

    float acc[4][10];
#pragma unroll
    for (int bb = 0; bb < 4; bb++)
#pragma unroll
        for (int o = 0; o < 10; o++) acc[bb][o] = 0.f;

    const int NF = 96 * GV;
    for (int f = threadIdx.x; f < NF; f += 256) {
        int c = f >> 10;
        float sc = g_bn_s[c], sh = g_bn_t[c];
        float w[10];
#pragma unroll
        for (int o = 0; o < 10; o++) w[o] = cw[(size_t)o * NF + f];
#pragma unroll
        for (int bb = 0; bb < 4; bb++) {
            float y = g_act[(size_t)(b0 + bb) * NF + f];
            float h = fmaxf(fmaf(y, sc, sh), 0.f);
#pragma unroll
            for (int o = 0; o < 10; o++) acc[bb][o] = fmaf(h, w[o], acc[bb][o]);
        }
    }

    __shared__ float part[8][40];
#pragma unroll
    for (int bb = 0; bb < 4; bb++)
#pragma unroll
        for (int o = 0; o < 10; o++) {
            float vsum = acc[bb][o];
#pragma unroll
            for (int off = 16; off > 0; off >>= 1)
                vsum += __shfl_down_sync(0xffffffffu, vsum, off);
            if (lane == 0) part[warp][bb * 10 + o] = vsum;
        }
    __syncthreads();
    if (threadIdx.x < 40) {
        float s = 0.f;
#pragma unroll
        for (int wq = 0; wq < 8; wq++) s += part[wq][threadIdx.x];
        int bb = threadIdx.x / 10, o = threadIdx.x % 10;
        out[(b0 + bb) * 10 + o] = s + cb[o];
    }
}

// ---------------- launch ----------------
extern "C" void kernel_launch(void* const* d_in, const int* in_sizes, int n_in,
                              void* d_out, int out_size) {
    (void)out_size;
    const float* x = (const float*)d_in[0];
    const float* w[7];
    const float* gg[7];
    const float* bb[7];

    // Input order disambiguation:
    //   dict order:      x, L, (w0,g0,b0), (w1,g1,b1), ..., clf_w, clf_b  -> in_sizes[3] == 96
    //   signature order: x, L, w0..w6, g0..g6, b0..b6, clf_w, clf_b      -> in_sizes[3] == 46080
    if (n_in >= 25 && in_sizes[3] == 96) {
        for (int i = 0; i < 7; i++) {
            w[i]  = (const float*)d_in[2 + 3 * i];
            gg[i] = (const float*)d_in[3 + 3 * i];
            bb[i] = (const float*)d_in[4 + 3 * i];
        }
    } else {
        for (int i = 0; i < 7; i++) {
            w[i]  = (const float*)d_in[2 + i];
            gg[i] = (const float*)d_in[9 + i];
            bb[i] = (const float*)d_in[16 + i];
        }
    }
    const float* clf_w = (const float*)d_in[23];
    const float* clf_b = (const float*)d_in[24];

    float* act_ptr = nullptr;
    cudaGetSymbolAddress((void**)&act_ptr, g_act);

    const int CIN[7]  = {3, 96, 96, 96, 192, 192, 192};
    const int FOUT[7] = {96, 96, 96, 192, 192, 192, 96};

    for (int l = 0; l < 7; l++) {
        const int C = CIN[l], F = FOUT[l], CK = C * KORD;

        // Chebyshev expansion (applies previous layer's BN+ReLU for l>0)
        cheb_expand<<<dim3(C, GB), GV>>>(l == 0 ? x : act_ptr, C, l == 0 ? 0 : 1);

        // batched GEMM: Y[b] = W_l @ Fk[b]
        dim3 grid((F + BM - 1) / BM, GV / BN, GB);
        gemm_batched<<<grid, 256>>>(w[l], F, CK);

        // BN batch statistics for this layer's output
        bn_mean<<<F, 256>>>(F);
        bn_var<<<F, 256>>>(F, gg[l], bb[l]);
    }

    classifier<<<32, 256>>>(clf_w, clf_b, (float*)d_out);
}

// round 2
// speedup vs baseline: 1.0044x; 1.0044x over previous
#include <cuda_runtime.h>

#define GV 1024
#define GB 128
#define KORD 5

// ---------------- scratch (device globals; no allocation) ----------------
__device__ float g_fk[(size_t)GB * 960 * GV];    // Chebyshev feature matrix [B, C*K, V] (max CK=960)
__device__ float g_act[(size_t)GB * 192 * GV];   // conv output Y [B, F, V] (max F=192)
__device__ float g_bn_s[192];                    // per-channel scale  g*rsqrt(var+eps)
__device__ float g_bn_t[192];                    // per-channel shift  b - mean*scale
__device__ float g_bn_mean[192];                 // per-channel mean (pass 1)

// 1/sqrt(deg) for deg in {2,3,4}
__device__ __forceinline__ float rsd_of(int i, int j) {
    int deg = (i > 0) + (i < 31) + (j > 0) + (j < 31);
    // deg is 2,3,4
    return (deg == 4) ? 0.5f : (deg == 3 ? 0.57735026918962576f : 0.70710678118654752f);
}

// ---------------- Chebyshev expansion (stencil recursion) ----------------
// in:  [B, C, V] activations (raw conv output of previous layer, or network input)
// out: g_fk[b, c*5+k, v],  k = 0..4
// If apply_bn: x <- relu(x*bn_s[c] + bn_t[c]) on load.
__global__ void cheb_expand(const float* __restrict__ in, int C, int apply_bn) {
    __shared__ float s[GV];
    const int v = threadIdx.x;
    const int c = blockIdx.x;
    const int b = blockIdx.y;
    const int i = v >> 5, j = v & 31;

    float x = in[((size_t)b * C + c) * GV + v];
    if (apply_bn) x = fmaxf(fmaf(x, g_bn_s[c], g_bn_t[c]), 0.0f);

    // L~ = -D^{-1/2} A D^{-1/2} : 4-neighbor stencil weights
    const float rv = rsd_of(i, j);
    const float w_up = (i > 0)  ? rv * rsd_of(i - 1, j) : 0.f;
    const float w_dn = (i < 31) ? rv * rsd_of(i + 1, j) : 0.f;
    const float w_lf = (j > 0)  ? rv * rsd_of(i, j - 1) : 0.f;
    const float w_rt = (j < 31) ? rv * rsd_of(i, j + 1) : 0.f;
    const int up = (i > 0)  ? v - 32 : v;
    const int dn = (i < 31) ? v + 32 : v;
    const int lf = (j > 0)  ? v - 1  : v;
    const int rt = (j < 31) ? v + 1  : v;

    const size_t base = ((size_t)b * (C * KORD) + (size_t)c * KORD) * GV + v;

    // T0
    g_fk[base] = x;
    s[v] = x;
    __syncthreads();
    // T1 = L x
    float t1 = -(w_up * s[up] + w_dn * s[dn] + w_lf * s[lf] + w_rt * s[rt]);
    g_fk[base + GV] = t1;

    float tp = x, tc = t1;
#pragma unroll
    for (int k = 2; k < KORD; k++) {
        __syncthreads();
        s[v] = tc;
        __syncthreads();
        float l = -(w_up * s[up] + w_dn * s[dn] + w_lf * s[lf] + w_rt * s[rt]);
        float tn = fmaf(2.0f, l, -tp);
        g_fk[base + (size_t)k * GV] = tn;
        tp = tc;
        tc = tn;
    }
}

// ---------------- batched GEMM:  Y[b] = W @ Fk[b] ----------------
// W:  [F, CK] row-major, Fk[b]: [CK, V] row-major, Y: [B, F, V]
#define BM 64
#define BN 128
#define BK 16

__global__ __launch_bounds__(256, 2)
void gemm_batched(const float* __restrict__ Wm, int F, int CK) {
    __shared__ float As[BK][BM];
    __shared__ float Bs[BK][BN];

    const int b  = blockIdx.z;
    const int m0 = blockIdx.x * BM;
    const int n0 = blockIdx.y * BN;
    const int t  = threadIdx.x;
    const int tm = t >> 4;        // 0..15 (4 rows each)
    const int tn = t & 15;        // 0..15 (8 cols each)

    const float* FkB = g_fk + (size_t)b * CK * GV;

    float acc[4][8];
#pragma unroll
    for (int ii = 0; ii < 4; ii++)
#pragma unroll
        for (int jj = 0; jj < 8; jj++) acc[ii][jj] = 0.f;

    const int ar  = t >> 2;        // 0..63  (A row)
    const int ac0 = (t & 3) * 4;   // A col group
    const int br  = t >> 4;        // 0..15  (B row)
    const int bc  = (t & 15) * 8;  // B col group

    for (int k0 = 0; k0 < CK; k0 += BK) {
        // load A tile (scalar, guarded: CK may be 15, F may be 96)
#pragma unroll
        for (int e = 0; e < 4; e++) {
            int kk = ac0 + e;
            int kg = k0 + kk, mg = m0 + ar;
            As[kk][ar] = (mg < F && kg < CK) ? Wm[(size_t)mg * CK + kg] : 0.f;
        }
        // load B tile (vectorized, V=1024 rows are 16B aligned)
        {
            int kg = k0 + br;
            if (kg < CK) {
                const float* src = FkB + (size_t)kg * GV + n0 + bc;
                *(float4*)&Bs[br][bc]     = *(const float4*)(src);
                *(float4*)&Bs[br][bc + 4] = *(const float4*)(src + 4);
            } else {
                float4 z = make_float4(0.f, 0.f, 0.f, 0.f);
                *(float4*)&Bs[br][bc]     = z;
                *(float4*)&Bs[br][bc + 4] = z;
            }
        }
        __syncthreads();
#pragma unroll
        for (int kk = 0; kk < BK; kk++) {
            float4 a  = *(const float4*)&As[kk][tm * 4];
            float4 q0 = *(const float4*)&Bs[kk][tn * 8];
            float4 q1 = *(const float4*)&Bs[kk][tn * 8 + 4];
            float av[4] = {a.x, a.y, a.z, a.w};
            float bv[8] = {q0.x, q0.y, q0.z, q0.w, q1.x, q1.y, q1.z, q1.w};
#pragma unroll
            for (int ii = 0; ii < 4; ii++)
#pragma unroll
                for (int jj = 0; jj < 8; jj++)
                    acc[ii][jj] = fmaf(av[ii], bv[jj], acc[ii][jj]);
        }
        __syncthreads();
    }

#pragma unroll
    for (int ii = 0; ii < 4; ii++) {
        int mg = m0 + tm * 4 + ii;
        if (mg < F) {
            float* dst = g_act + ((size_t)b * F + mg) * GV + n0 + tn * 8;
            *(float4*)dst       = make_float4(acc[ii][0], acc[ii][1], acc[ii][2], acc[ii][3]);
            *(float4*)(dst + 4) = make_float4(acc[ii][4], acc[ii][5], acc[ii][6], acc[ii][7]);
        }
    }
}

// ---------------- BN statistics (two-pass for numerical safety) ----------------
__global__ void bn_mean(int F) {
    __shared__ float red[256];
    const int f = blockIdx.x;
    float sum = 0.f;
    for (int idx = threadIdx.x; idx < GB * GV; idx += 256) {
        int b = idx >> 10, v = idx & (GV - 1);
        sum += g_act[((size_t)b * F + f) * GV + v];
    }
    red[threadIdx.x] = sum;
    __syncthreads();
    for (int s = 128; s > 0; s >>= 1) {
        if (threadIdx.x < s) red[threadIdx.x] += red[threadIdx.x + s];
        __syncthreads();
    }
    if (threadIdx.x == 0) g_bn_mean[f] = red[0] / (float)(GB * GV);
}

__global__ void bn_var(int F, const float* __restrict__ gamma, const float* __restrict__ beta) {
    __shared__ float red[256];
    const int f = blockIdx.x;
    const float m = g_bn_mean[f];
    float sq = 0.f;
    for (int idx = threadIdx.x; idx < GB * GV; idx += 256) {
        int b = idx >> 10, v = idx & (GV - 1);
        float d = g_act[((size_t)b * F + f) * GV + v] - m;
        sq = fmaf(d, d, sq);
    }
    red[threadIdx.x] = sq;
    __syncthreads();
    for (int s = 128; s > 0; s >>= 1) {
        if (threadIdx.x < s) red[threadIdx.x] += red[threadIdx.x + s];
        __syncthreads();
    }
    if (threadIdx.x == 0) {
        float var = red[0] / (float)(GB * GV);
        float sc  = gamma[f] * rsqrtf(var + 1e-5f);
        g_bn_s[f] = sc;
        g_bn_t[f] = beta[f] - m * sc;
    }
}

// ---------------- classifier: out[b,o] = sum_f relu(bn(Y6))[b,f] * clf_w[o,f] + clf_b[o] ----------------
__global__ void classifier(const float* __restrict__ cw, const float* __restrict__ cb,
                           float* __restrict__ out) {
    const int b0   = blockIdx.x * 4;
    const int lane = threadIdx.x & 31;
    const int warp = threadIdx.x >> 5;

    float acc[4][10];
#pragma unroll
    for (int bb = 0; bb < 4; bb++)
#pragma unroll
        for (int o = 0; o < 10; o++) acc[bb][o] = 0.f;

    const int NF = 96 * GV;
    for (int f = threadIdx.x; f < NF; f += 256) {
        int c = f >> 10;
        float sc = g_bn_s[c], sh = g_bn_t[c];
        float w[10];
#pragma unroll
        for (int o = 0; o < 10; o++) w[o] = cw[(size_t)o * NF + f];
#pragma unroll
        for (int bb = 0; bb < 4; bb++) {
            float y = g_act[(size_t)(b0 + bb) * NF + f];
            float h = fmaxf(fmaf(y, sc, sh), 0.f);
#pragma unroll
            for (int o = 0; o < 10; o++) acc[bb][o] = fmaf(h, w[o], acc[bb][o]);
        }
    }

    __shared__ float part[8][40];
#pragma unroll
    for (int bb = 0; bb < 4; bb++)
#pragma unroll
        for (int o = 0; o < 10; o++) {
            float vsum = acc[bb][o];
#pragma unroll
            for (int off = 16; off > 0; off >>= 1)
                vsum += __shfl_down_sync(0xffffffffu, vsum, off);
            if (lane == 0) part[warp][bb * 10 + o] = vsum;
        }
    __syncthreads();
    if (threadIdx.x < 40) {
        float s = 0.f;
#pragma unroll
        for (int wq = 0; wq < 8; wq++) s += part[wq][threadIdx.x];
        int bb = threadIdx.x / 10, o = threadIdx.x % 10;
        out[(b0 + bb) * 10 + o] = s + cb[o];
    }
}

// ---------------- launch ----------------
extern "C" void kernel_launch(void* const* d_in, const int* in_sizes, int n_in,
                              void* d_out, int out_size) {
    (void)out_size;
    const float* x = (const float*)d_in[0];
    const float* w[7];
    const float* gg[7];
    const float* bb[7];

    // Input order disambiguation:
    //   dict order:      x, L, (w0,g0,b0), (w1,g1,b1), ..., clf_w, clf_b  -> in_sizes[3] == 96
    //   signature order: x, L, w0..w6, g0..g6, b0..b6, clf_w, clf_b      -> in_sizes[3] == 46080
    if (n_in >= 25 && in_sizes[3] == 96) {
        for (int i = 0; i < 7; i++) {
            w[i]  = (const float*)d_in[2 + 3 * i];
            gg[i] = (const float*)d_in[3 + 3 * i];
            bb[i] = (const float*)d_in[4 + 3 * i];
        }
    } else {
        for (int i = 0; i < 7; i++) {
            w[i]  = (const float*)d_in[2 + i];
            gg[i] = (const float*)d_in[9 + i];
            bb[i] = (const float*)d_in[16 + i];
        }
    }
    const float* clf_w = (const float*)d_in[23];
    const float* clf_b = (const float*)d_in[24];

    float* act_ptr = nullptr;
    cudaGetSymbolAddress((void**)&act_ptr, g_act);

    const int CIN[7]  = {3, 96, 96, 96, 192, 192, 192};
    const int FOUT[7] = {96, 96, 96, 192, 192, 192, 96};

    for (int l = 0; l < 7; l++) {
        const int C = CIN[l], F = FOUT[l], CK = C * KORD;

        // Chebyshev expansion (applies previous layer's BN+ReLU for l>0)
        cheb_expand<<<dim3(C, GB), GV>>>(l == 0 ? x : act_ptr, C, l == 0 ? 0 : 1);

        // batched GEMM: Y[b] = W_l @ Fk[b]
        dim3 grid((F + BM - 1) / BM, GV / BN, GB);
        gemm_batched<<<grid, 256>>>(w[l], F, CK);

        // BN batch statistics for this layer's output
        bn_mean<<<F, 256>>>(F);
        bn_var<<<F, 256>>>(F, gg[l], bb[l]);
    }

    classifier<<<32, 256>>>(clf_w, clf_b, (float*)d_out);
}

// round 4
// speedup vs baseline: 1.1316x; 1.1266x over previous
#include <cuda_runtime.h>
#include <cstdint>

#define GV 1024
#define GB 128
#define NN (GB * GV)          // 131072 columns (channel-major)
#define KORD 5

// ---------------- scratch (device globals; no allocation) ----------------
__device__ float g_fk[(size_t)960 * NN];   // Chebyshev features [CK, B*V]
__device__ float g_act[(size_t)192 * NN];  // conv output Y [F, B*V]
__device__ float g_bn_s[192];
__device__ float g_bn_t[192];

// ---------------- packed f32x2 FMA (FFMA2) ----------------
#define FMA2(d, a, b, c) \
    asm("fma.rn.f32x2 %0, %1, %2, %3;" : "=l"(d) : "l"(a), "l"(b), "l"(c))

__device__ __forceinline__ float2 upk(unsigned long long v) {
    float2 r;
    asm("mov.b64 {%0, %1}, %2;" : "=f"(r.x), "=f"(r.y) : "l"(v));
    return r;
}

// ---------------- Chebyshev expansion (grid stencil), channel-major ----------------
__device__ __forceinline__ float rsd_of(int i, int j) {
    int deg = (i > 0) + (i < 31) + (j > 0) + (j < 31);
    return (deg == 4) ? 0.5f : (deg == 3 ? 0.57735026918962576f : 0.70710678118654752f);
}

__global__ void cheb_expand(const float* __restrict__ xin, int C, int layer0) {
    __shared__ float s[GV];
    const int v = threadIdx.x;
    const int c = blockIdx.x;
    const int b = blockIdx.y;
    const int i = v >> 5, j = v & 31;

    float x;
    if (layer0) {
        x = xin[((size_t)b * C + c) * GV + v];
    } else {
        x = g_act[(size_t)c * NN + (size_t)b * GV + v];
        x = fmaxf(fmaf(x, g_bn_s[c], g_bn_t[c]), 0.0f);
    }

    const float rv = rsd_of(i, j);
    const float w_up = (i > 0)  ? rv * rsd_of(i - 1, j) : 0.f;
    const float w_dn = (i < 31) ? rv * rsd_of(i + 1, j) : 0.f;
    const float w_lf = (j > 0)  ? rv * rsd_of(i, j - 1) : 0.f;
    const float w_rt = (j < 31) ? rv * rsd_of(i, j + 1) : 0.f;
    const int up = (i > 0)  ? v - 32 : v;
    const int dn = (i < 31) ? v + 32 : v;
    const int lf = (j > 0)  ? v - 1  : v;
    const int rt = (j < 31) ? v + 1  : v;

    float* out = g_fk + (size_t)(c * KORD) * NN + (size_t)b * GV + v;

    out[0] = x;
    s[v] = x;
    __syncthreads();
    float t1 = -(w_up * s[up] + w_dn * s[dn] + w_lf * s[lf] + w_rt * s[rt]);
    out[NN] = t1;

    float tp = x, tc = t1;
#pragma unroll
    for (int k = 2; k < KORD; k++) {
        __syncthreads();
        s[v] = tc;
        __syncthreads();
        float l = -(w_up * s[up] + w_dn * s[dn] + w_lf * s[lf] + w_rt * s[rt]);
        float tn = fmaf(2.0f, l, -tp);
        out[(size_t)k * NN] = tn;
        tp = tc;
        tc = tn;
    }
}

// ---------------- GEMM via packed FFMA2:  Y = W @ Fk ----------------
// W: [F, CK] row-major.  Fk: [CK, NN].  Y: [F, NN].
// Tile: 96(M) x 128(N) x 16(K), 256 threads, each thread 6m x 8n.
// A is stored DUPLICATED in smem ([k][2m] = [k][2m+1]) so {a,a} f32x2
// operands come from a single LDS.128.
#define BM 96
#define BN 128
#define BK 16

__global__ void __launch_bounds__(256, 2)
gemm_f32x2(const float* __restrict__ Wm, int F, int CK) {
    __shared__ __align__(16) float As[2][BK][2 * BM];  // 24,576 B
    __shared__ __align__(16) float Bs[2][BK][BN];      // 16,384 B

    const int m0 = blockIdx.x * BM;
    const int n0 = blockIdx.y * BN;
    const int tid = threadIdx.x;
    const int tx = tid & 15;   // n group (8 cols)
    const int ty = tid >> 4;   // m group (6 rows)

    const float* Wb = Wm + (size_t)m0 * CK;

    unsigned long long acc[6][4];
#pragma unroll
    for (int im = 0; im < 6; im++)
#pragma unroll
        for (int jn = 0; jn < 4; jn++) acc[im][jn] = 0ULL;

    const int ns = (CK + BK - 1) / BK;

    float  pa[6];
    float4 pb[2];

    // ---- prefetch + store stage 0 ----
#pragma unroll
    for (int i = 0; i < 6; i++) {
        int lin = tid * 6 + i;        // 0..1535
        int m = lin >> 4, kk = lin & 15;
        pa[i] = (kk < CK) ? Wb[(size_t)m * CK + kk] : 0.f;
    }
#pragma unroll
    for (int j = 0; j < 2; j++) {
        int u = tid + j * 256;        // 0..511
        int kk = u >> 5, jj = u & 31;
        pb[j] = (kk < CK) ? *(const float4*)(g_fk + (size_t)kk * NN + n0 + jj * 4)
                          : make_float4(0.f, 0.f, 0.f, 0.f);
    }
#pragma unroll
    for (int i = 0; i < 6; i++) {
        int lin = tid * 6 + i;
        int m = lin >> 4, kk = lin & 15;
        *(float2*)&As[0][kk][2 * m] = make_float2(pa[i], pa[i]);
    }
#pragma unroll
    for (int j = 0; j < 2; j++) {
        int u = tid + j * 256;
        int kk = u >> 5, jj = u & 31;
        *(float4*)&Bs[0][kk][jj * 4] = pb[j];
    }
    __syncthreads();

    for (int s = 0; s < ns; s++) {
        const int buf = s & 1;
        const int k1 = (s + 1) * BK;

        // issue global loads for next stage (hidden behind compute)
        if (s + 1 < ns) {
#pragma unroll
            for (int i = 0; i < 6; i++) {
                int lin = tid * 6 + i;
                int m = lin >> 4, kk = lin & 15;
                pa[i] = (k1 + kk < CK) ? Wb[(size_t)m * CK + k1 + kk] : 0.f;
            }
#pragma unroll
            for (int j = 0; j < 2; j++) {
                int u = tid + j * 256;
                int kk = u >> 5, jj = u & 31;
                pb[j] = (k1 + kk < CK)
                          ? *(const float4*)(g_fk + (size_t)(k1 + kk) * NN + n0 + jj * 4)
                          : make_float4(0.f, 0.f, 0.f, 0.f);
            }
        }

        // ---- compute on current buffer ----
        {
            const float(*A)[2 * BM] = As[buf];
            const float(*Bt)[BN]    = Bs[buf];
#pragma unroll 4
            for (int kk = 0; kk < BK; kk++) {
                ulonglong2 a0 = *(const ulonglong2*)&A[kk][ty * 12];
                ulonglong2 a1 = *(const ulonglong2*)&A[kk][ty * 12 + 4];
                ulonglong2 a2 = *(const ulonglong2*)&A[kk][ty * 12 + 8];
                ulonglong2 b0 = *(const ulonglong2*)&Bt[kk][tx * 8];
                ulonglong2 b1 = *(const ulonglong2*)&Bt[kk][tx * 8 + 4];
                unsigned long long av[6] = {a0.x, a0.y, a1.x, a1.y, a2.x, a2.y};
                unsigned long long bv[4] = {b0.x, b0.y, b1.x, b1.y};
#pragma unroll
                for (int im = 0; im < 6; im++)
#pragma unroll
                    for (int jn = 0; jn < 4; jn++)
                        FMA2(acc[im][jn], av[im], bv[jn], acc[im][jn]);
            }
        }

        // ---- stash next stage into the other buffer ----
        if (s + 1 < ns) {
            const int nb = buf ^ 1;
#pragma unroll
            for (int i = 0; i < 6; i++) {
                int lin = tid * 6 + i;
                int m = lin >> 4, kk = lin & 15;
                *(float2*)&As[nb][kk][2 * m] = make_float2(pa[i], pa[i]);
            }
#pragma unroll
            for (int j = 0; j < 2; j++) {
                int u = tid + j * 256;
                int kk = u >> 5, jj = u & 31;
                *(float4*)&Bs[nb][kk][jj * 4] = pb[j];
            }
        }
        __syncthreads();
    }

    // ---- epilogue ----
#pragma unroll
    for (int im = 0; im < 6; im++) {
        const int row = m0 + ty * 6 + im;
        float* dst = g_act + (size_t)row * NN + n0 + tx * 8;
        float2 f0 = upk(acc[im][0]);
        float2 f1 = upk(acc[im][1]);
        float2 f2 = upk(acc[im][2]);
        float2 f3 = upk(acc[im][3]);
        *(float4*)dst       = make_float4(f0.x, f0.y, f1.x, f1.y);
        *(float4*)(dst + 4) = make_float4(f2.x, f2.y, f3.x, f3.y);
    }
}

// ---------------- BN statistics: single pass, double accumulation ----------------
__global__ void bn_stats(const float* __restrict__ gamma, const float* __restrict__ beta) {
    __shared__ double rs[512];
    __shared__ double rq[512];
    const int f = blockIdx.x;
    const float* row = g_act + (size_t)f * NN;

    double s0 = 0, s1 = 0, q0 = 0, q1 = 0;
    for (int i = threadIdx.x * 8; i < NN; i += 512 * 8) {
        float4 a = *(const float4*)(row + i);
        float4 b = *(const float4*)(row + i + 4);
        s0 += (double)a.x + (double)a.y + (double)a.z + (double)a.w;
        s1 += (double)b.x + (double)b.y + (double)b.z + (double)b.w;
        q0 += (double)a.x * a.x + (double)a.y * a.y + (double)a.z * a.z + (double)a.w * a.w;
        q1 += (double)b.x * b.x + (double)b.y * b.y + (double)b.z * b.z + (double)b.w * b.w;
    }
    rs[threadIdx.x] = s0 + s1;
    rq[threadIdx.x] = q0 + q1;
    __syncthreads();
    for (int st = 256; st > 0; st >>= 1) {
        if (threadIdx.x < st) {
            rs[threadIdx.x] += rs[threadIdx.x + st];
            rq[threadIdx.x] += rq[threadIdx.x + st];
        }
        __syncthreads();
    }
    if (threadIdx.x == 0) {
        double mean = rs[0] / (double)NN;
        double var  = rq[0] / (double)NN - mean * mean;
        float sc = gamma[f] * rsqrtf((float)var + 1e-5f);
        g_bn_s[f] = sc;
        g_bn_t[f] = beta[f] - (float)mean * sc;
    }
}

// ---------------- classifier ----------------
__global__ void classifier(const float* __restrict__ cw, const float* __restrict__ cb,
                           float* __restrict__ out) {
    const int b0   = blockIdx.x * 4;
    const int lane = threadIdx.x & 31;
    const int warp = threadIdx.x >> 5;

    float acc[4][10];
#pragma unroll
    for (int bb = 0; bb < 4; bb++)
#pragma unroll
        for (int o = 0; o < 10; o++) acc[bb][o] = 0.f;

    const int NF = 96 * GV;
    for (int f = threadIdx.x; f < NF; f += 256) {
        int c = f >> 10, v = f & (GV - 1);
        float sc = g_bn_s[c], sh = g_bn_t[c];
        float w[10];
#pragma unroll
        for (int o = 0; o < 10; o++) w[o] = cw[(size_t)o * NF + f];
#pragma unroll
        for (int bb = 0; bb < 4; bb++) {
            float y = g_act[(size_t)c * NN + (size_t)(b0 + bb) * GV + v];
            float h = fmaxf(fmaf(y, sc, sh), 0.f);
#pragma unroll
            for (int o = 0; o < 10; o++) acc[bb][o] = fmaf(h, w[o], acc[bb][o]);
        }
    }

    __shared__ float part[8][40];
#pragma unroll
    for (int bb = 0; bb < 4; bb++)
#pragma unroll
        for (int o = 0; o < 10; o++) {
            float vsum = acc[bb][o];
#pragma unroll
            for (int off = 16; off > 0; off >>= 1)
                vsum += __shfl_down_sync(0xffffffffu, vsum, off);
            if (lane == 0) part[warp][bb * 10 + o] = vsum;
        }
    __syncthreads();
    if (threadIdx.x < 40) {
        float ssum = 0.f;
#pragma unroll
        for (int wq = 0; wq < 8; wq++) ssum += part[wq][threadIdx.x];
        int bb = threadIdx.x / 10, o = threadIdx.x % 10;
        out[(b0 + bb) * 10 + o] = ssum + cb[o];
    }
}

// ---------------- launch ----------------
extern "C" void kernel_launch(void* const* d_in, const int* in_sizes, int n_in,
                              void* d_out, int out_size) {
    (void)out_size;
    const float* x = (const float*)d_in[0];
    const float* w[7];
    const float* gg[7];
    const float* bb[7];

    if (n_in >= 25 && in_sizes[3] == 96) {  // dict order (w,g,b per layer)
        for (int i = 0; i < 7; i++) {
            w[i]  = (const float*)d_in[2 + 3 * i];
            gg[i] = (const float*)d_in[3 + 3 * i];
            bb[i] = (const float*)d_in[4 + 3 * i];
        }
    } else {                                // signature order
        for (int i = 0; i < 7; i++) {
            w[i]  = (const float*)d_in[2 + i];
            gg[i] = (const float*)d_in[9 + i];
            bb[i] = (const float*)d_in[16 + i];
        }
    }
    const float* clf_w = (const float*)d_in[23];
    const float* clf_b = (const float*)d_in[24];

    const int CIN[7]  = {3, 96, 96, 96, 192, 192, 192};
    const int FOUT[7] = {96, 96, 96, 192, 192, 192, 96};

    for (int l = 0; l < 7; l++) {
        const int C = CIN[l], F = FOUT[l], CK = C * KORD;

        cheb_expand<<<dim3(C, GB), GV>>>(x, C, l == 0 ? 1 : 0);

        // m-tiles fastest so both m-tiles of an n-tile share B via L2
        dim3 grid(F / BM, NN / BN);
        gemm_f32x2<<<grid, 256>>>(w[l], F, CK);

        bn_stats<<<F, 512>>>(gg[l], bb[l]);
    }

    classifier<<<32, 256>>>(clf_w, clf_b, (float*)d_out);
}

// round 6
// speedup vs baseline: 1.9771x; 1.7472x over previous
#include <cuda_runtime.h>
#include <cuda_bf16.h>
#include <cstdint>

#define GV 1024
#define GB 128
#define NN (GB * GV)          // 131072 columns (channel-major)
#define KORD 5
#define CKP 960               // padded K stride for split weights

// ---------------- scratch (device globals; no allocation) ----------------
__device__ float g_fk[(size_t)960 * NN];    // Chebyshev features [CK, B*V] fp32
__device__ float g_act[(size_t)192 * NN];   // conv output Y [F, B*V] fp32
__device__ float g_bn_s[192];
__device__ float g_bn_t[192];
__device__ __nv_bfloat16 g_wh[192 * CKP];   // W hi plane [F][960]
__device__ __nv_bfloat16 g_wl[192 * CKP];   // W lo plane [F][960]

// ---------------- helpers ----------------
__device__ __forceinline__ uint32_t smem_u32(const void* p) {
    uint32_t a;
    asm("{ .reg .u64 t; cvta.to.shared.u64 t, %1; cvt.u32.u64 %0, t; }" : "=r"(a) : "l"(p));
    return a;
}
// pack two floats' bf16-hi and bf16-lo into words (low half = first arg)
__device__ __forceinline__ void split_pack(float e, float o, uint32_t& wh, uint32_t& wl) {
    __nv_bfloat16 he = __float2bfloat16_rn(e), ho = __float2bfloat16_rn(o);
    float re = e - __bfloat162float(he), ro = o - __bfloat162float(ho);
    __nv_bfloat16 le = __float2bfloat16_rn(re), lo = __float2bfloat16_rn(ro);
    wh = (uint32_t)__bfloat16_as_ushort(he) | ((uint32_t)__bfloat16_as_ushort(ho) << 16);
    wl = (uint32_t)__bfloat16_as_ushort(le) | ((uint32_t)__bfloat16_as_ushort(lo) << 16);
}

__device__ __forceinline__ void mma_bf16(float* d, const uint32_t* a, const uint32_t* b) {
    asm volatile(
        "mma.sync.aligned.m16n8k16.row.col.f32.bf16.bf16.f32 "
        "{%0,%1,%2,%3}, {%4,%5,%6,%7}, {%8,%9}, {%0,%1,%2,%3};"
        : "+f"(d[0]), "+f"(d[1]), "+f"(d[2]), "+f"(d[3])
        : "r"(a[0]), "r"(a[1]), "r"(a[2]), "r"(a[3]), "r"(b[0]), "r"(b[1]));
}

#define CP_ASYNC16(dst, src) \
    asm volatile("cp.async.ca.shared.global [%0], [%1], 16;" :: "r"(dst), "l"(src) : "memory")
#define CP_COMMIT() asm volatile("cp.async.commit_group;" ::: "memory")
#define CP_WAIT0()  asm volatile("cp.async.wait_group 0;" ::: "memory")

// ---------------- W split: fp32 -> bf16 hi/lo planes, zero-padded to CKP ----------------
__global__ void wsplit(const float* __restrict__ W, int F, int CK) {
    int idx = blockIdx.x * 256 + threadIdx.x;
    if (idx >= F * CKP) return;
    int k = idx % CKP;
    int f = idx / CKP;
    float v = (k < CK) ? W[(size_t)f * CK + k] : 0.f;
    __nv_bfloat16 h = __float2bfloat16_rn(v);
    g_wh[idx] = h;
    g_wl[idx] = __float2bfloat16_rn(v - __bfloat162float(h));
}

// ---------------- Chebyshev expansion (grid stencil), channel-major ----------------
__device__ __forceinline__ float rsd_of(int i, int j) {
    int deg = (i > 0) + (i < 31) + (j > 0) + (j < 31);
    return (deg == 4) ? 0.5f : (deg == 3 ? 0.57735026918962576f : 0.70710678118654752f);
}

__global__ void cheb_expand(const float* __restrict__ xin, int C, int layer0) {
    __shared__ float s[GV];
    const int v = threadIdx.x;
    const int c = blockIdx.x;
    const int b = blockIdx.y;
    const int i = v >> 5, j = v & 31;

    float x;
    if (layer0) {
        x = xin[((size_t)b * C + c) * GV + v];
    } else {
        x = g_act[(size_t)c * NN + (size_t)b * GV + v];
        x = fmaxf(fmaf(x, g_bn_s[c], g_bn_t[c]), 0.0f);
    }

    const float rv = rsd_of(i, j);
    const float w_up = (i > 0)  ? rv * rsd_of(i - 1, j) : 0.f;
    const float w_dn = (i < 31) ? rv * rsd_of(i + 1, j) : 0.f;
    const float w_lf = (j > 0)  ? rv * rsd_of(i, j - 1) : 0.f;
    const float w_rt = (j < 31) ? rv * rsd_of(i, j + 1) : 0.f;
    const int up = (i > 0)  ? v - 32 : v;
    const int dn = (i < 31) ? v + 32 : v;
    const int lf = (j > 0)  ? v - 1  : v;
    const int rt = (j < 31) ? v + 1  : v;

    float* out = g_fk + (size_t)(c * KORD) * NN + (size_t)b * GV + v;

    out[0] = x;
    s[v] = x;
    __syncthreads();
    float t1 = -(w_up * s[up] + w_dn * s[dn] + w_lf * s[lf] + w_rt * s[rt]);
    out[NN] = t1;

    float tp = x, tc = t1;
#pragma unroll
    for (int k = 2; k < KORD; k++) {
        __syncthreads();
        s[v] = tc;
        __syncthreads();
        float l = -(w_up * s[up] + w_dn * s[dn] + w_lf * s[lf] + w_rt * s[rt]);
        float tn = fmaf(2.0f, l, -tp);
        out[(size_t)k * NN] = tn;
        tp = tc;
        tc = tn;
    }
}

// ---------------- tensor-core GEMM via mma.sync (bf16 hi/lo 3-term) ----------------
// Y[96m x 128n] per CTA; BK=32. 8 warps = 2(m) x 4(n); warp tile 48m x 32n.
// smem per stage: Ah[96][80B] Al Bh[128][80B] Bl  (row stride 20 words, pad 4)
#define ROWB 80
#define SZ_A (96 * ROWB)            // 7680
#define SZ_B (128 * ROWB)           // 10240
#define OFF_AH 0
#define OFF_AL SZ_A
#define OFF_BH (2 * SZ_A)
#define OFF_BL (2 * SZ_A + SZ_B)
#define STAGE  (2 * SZ_A + 2 * SZ_B)  // 35840
#define SMEM_GEMM (2 * STAGE)         // 71680

__global__ void __launch_bounds__(256, 2)
gemm_mma(int F, int CK) {
    extern __shared__ char smem[];
    const uint32_t sbase = smem_u32(smem);

    const int tid  = threadIdx.x;
    const int lane = tid & 31;
    const int wid  = tid >> 5;
    const int wm   = wid & 1;        // 0..1  (m)
    const int wn   = wid >> 1;       // 0..3  (n)
    const int g    = lane >> 2;      // 0..7
    const int t4   = lane & 3;       // 0..3

    const int m0 = blockIdx.x * 96;
    const int n0 = blockIdx.y * 128;
    const int ns = (CK + 31) >> 5;

    float acc[3][4][4];
#pragma unroll
    for (int a = 0; a < 3; a++)
#pragma unroll
        for (int b = 0; b < 4; b++)
#pragma unroll
            for (int c = 0; c < 4; c++) acc[a][b][c] = 0.f;

    // ---- per-thread load assignments ----
    // A (cp.async): 768 chunks = plane(2) x row(96) x q(4); 3 per thread
    // B (LDG f2):   4 units: kp = (tid>>6)+4j, np = tid&63
    const int np  = tid & 63;
    const int kpb = tid >> 6;

    float2 ve[4], vo[4];

    // ---- prologue: stage 0 ----
    {
        const int k0 = 0;
#pragma unroll
        for (int i = 0; i < 3; i++) {
            int e = tid + 256 * i;
            int p = e >= 384;
            int id = e - 384 * p;
            int r = id >> 2, q = id & 3;
            const __nv_bfloat16* src = (p ? g_wl : g_wh) + (size_t)(m0 + r) * CKP + k0 + q * 8;
            CP_ASYNC16(sbase + (p ? OFF_AL : OFF_AH) + r * ROWB + q * 16, src);
        }
        CP_COMMIT();
#pragma unroll
        for (int j = 0; j < 4; j++) {
            int kp = kpb + 4 * j;
            int ke = k0 + 2 * kp;
            ve[j] = (ke < CK)     ? *(const float2*)(g_fk + (size_t)ke * NN + n0 + 2 * np)
                                  : make_float2(0.f, 0.f);
            vo[j] = (ke + 1 < CK) ? *(const float2*)(g_fk + (size_t)(ke + 1) * NN + n0 + 2 * np)
                                  : make_float2(0.f, 0.f);
        }
#pragma unroll
        for (int j = 0; j < 4; j++) {
            int kp = kpb + 4 * j;
            uint32_t wh0, wl0, wh1, wl1;
            split_pack(ve[j].x, vo[j].x, wh0, wl0);
            split_pack(ve[j].y, vo[j].y, wh1, wl1);
            char* bh = smem + OFF_BH;
            char* bl = smem + OFF_BL;
            *(uint32_t*)(bh + (2 * np)     * ROWB + kp * 4) = wh0;
            *(uint32_t*)(bh + (2 * np + 1) * ROWB + kp * 4) = wh1;
            *(uint32_t*)(bl + (2 * np)     * ROWB + kp * 4) = wl0;
            *(uint32_t*)(bl + (2 * np + 1) * ROWB + kp * 4) = wl1;
        }
        CP_WAIT0();
        __syncthreads();
    }

    for (int s = 0; s < ns; s++) {
        const int buf = (s & 1) * STAGE;
        const int nbuf = STAGE - buf;
        const bool more = (s + 1 < ns);

        // issue next-stage loads
        if (more) {
            const int k1 = (s + 1) * 32;
#pragma unroll
            for (int i = 0; i < 3; i++) {
                int e = tid + 256 * i;
                int p = e >= 384;
                int id = e - 384 * p;
                int r = id >> 2, q = id & 3;
                const __nv_bfloat16* src = (p ? g_wl : g_wh) + (size_t)(m0 + r) * CKP + k1 + q * 8;
                CP_ASYNC16(sbase + nbuf + (p ? OFF_AL : OFF_AH) + r * ROWB + q * 16, src);
            }
            CP_COMMIT();
#pragma unroll
            for (int j = 0; j < 4; j++) {
                int kp = kpb + 4 * j;
                int ke = k1 + 2 * kp;
                ve[j] = (ke < CK)     ? *(const float2*)(g_fk + (size_t)ke * NN + n0 + 2 * np)
                                      : make_float2(0.f, 0.f);
                vo[j] = (ke + 1 < CK) ? *(const float2*)(g_fk + (size_t)(ke + 1) * NN + n0 + 2 * np)
                                      : make_float2(0.f, 0.f);
            }
        }

        // ---- compute from current buffer ----
        const char* Ah = smem + buf + OFF_AH;
        const char* Al = smem + buf + OFF_AL;
        const char* Bh = smem + buf + OFF_BH;
        const char* Bl = smem + buf + OFF_BL;
#pragma unroll
        for (int c = 0; c < 2; c++) {
            uint32_t ah[3][4], al[3][4];
#pragma unroll
            for (int mf = 0; mf < 3; mf++) {
                int row = wm * 48 + mf * 16 + g;
                int w0 = (c * 8 + t4) * 4;
                ah[mf][0] = *(const uint32_t*)(Ah + row * ROWB + w0);
                ah[mf][1] = *(const uint32_t*)(Ah + (row + 8) * ROWB + w0);
                ah[mf][2] = *(const uint32_t*)(Ah + row * ROWB + w0 + 16);
                ah[mf][3] = *(const uint32_t*)(Ah + (row + 8) * ROWB + w0 + 16);
                al[mf][0] = *(const uint32_t*)(Al + row * ROWB + w0);
                al[mf][1] = *(const uint32_t*)(Al + (row + 8) * ROWB + w0);
                al[mf][2] = *(const uint32_t*)(Al + row * ROWB + w0 + 16);
                al[mf][3] = *(const uint32_t*)(Al + (row + 8) * ROWB + w0 + 16);
            }
#pragma unroll
            for (int nf = 0; nf < 4; nf++) {
                int nrow = wn * 32 + nf * 8 + g;
                int w0 = (c * 8 + t4) * 4;
                uint32_t bh[2], bl[2];
                bh[0] = *(const uint32_t*)(Bh + nrow * ROWB + w0);
                bh[1] = *(const uint32_t*)(Bh + nrow * ROWB + w0 + 16);
                bl[0] = *(const uint32_t*)(Bl + nrow * ROWB + w0);
                bl[1] = *(const uint32_t*)(Bl + nrow * ROWB + w0 + 16);
#pragma unroll
                for (int mf = 0; mf < 3; mf++) {
                    mma_bf16(acc[mf][nf], ah[mf], bh);
                    mma_bf16(acc[mf][nf], al[mf], bh);
                    mma_bf16(acc[mf][nf], ah[mf], bl);
                }
            }
        }

        // ---- store next-stage B, finish A ----
        if (more) {
#pragma unroll
            for (int j = 0; j < 4; j++) {
                int kp = kpb + 4 * j;
                uint32_t wh0, wl0, wh1, wl1;
                split_pack(ve[j].x, vo[j].x, wh0, wl0);
                split_pack(ve[j].y, vo[j].y, wh1, wl1);
                char* bh = smem + nbuf + OFF_BH;
                char* bl = smem + nbuf + OFF_BL;
                *(uint32_t*)(bh + (2 * np)     * ROWB + kp * 4) = wh0;
                *(uint32_t*)(bh + (2 * np + 1) * ROWB + kp * 4) = wh1;
                *(uint32_t*)(bl + (2 * np)     * ROWB + kp * 4) = wl0;
                *(uint32_t*)(bl + (2 * np + 1) * ROWB + kp * 4) = wl1;
            }
            CP_WAIT0();
        }
        __syncthreads();
    }

    // ---- epilogue: fragments -> g_act [F][NN] ----
#pragma unroll
    for (int mf = 0; mf < 3; mf++) {
        int mrow = m0 + wm * 48 + mf * 16 + g;
#pragma unroll
        for (int nf = 0; nf < 4; nf++) {
            int col = n0 + wn * 32 + nf * 8 + 2 * t4;
            *(float2*)(g_act + (size_t)mrow * NN + col) =
                make_float2(acc[mf][nf][0], acc[mf][nf][1]);
            *(float2*)(g_act + (size_t)(mrow + 8) * NN + col) =
                make_float2(acc[mf][nf][2], acc[mf][nf][3]);
        }
    }
}

// ---------------- BN statistics: single pass, double accumulation ----------------
__global__ void bn_stats(const float* __restrict__ gamma, const float* __restrict__ beta) {
    __shared__ double rs[512];
    __shared__ double rq[512];
    const int f = blockIdx.x;
    const float* row = g_act + (size_t)f * NN;

    double s0 = 0, q0 = 0;
    for (int i = threadIdx.x * 4; i < NN; i += 512 * 4) {
        float4 a = *(const float4*)(row + i);
        s0 += (double)a.x + (double)a.y + (double)a.z + (double)a.w;
        q0 += (double)a.x * a.x + (double)a.y * a.y + (double)a.z * a.z + (double)a.w * a.w;
    }
    rs[threadIdx.x] = s0;
    rq[threadIdx.x] = q0;
    __syncthreads();
    for (int st = 256; st > 0; st >>= 1) {
        if (threadIdx.x < st) {
            rs[threadIdx.x] += rs[threadIdx.x + st];
            rq[threadIdx.x] += rq[threadIdx.x + st];
        }
        __syncthreads();
    }
    if (threadIdx.x == 0) {
        double mean = rs[0] / (double)NN;
        double var  = rq[0] / (double)NN - mean * mean;
        float sc = gamma[f] * rsqrtf((float)var + 1e-5f);
        g_bn_s[f] = sc;
        g_bn_t[f] = beta[f] - (float)mean * sc;
    }
}

// ---------------- classifier ----------------
__global__ void classifier(const float* __restrict__ cw, const float* __restrict__ cb,
                           float* __restrict__ out) {
    const int b0   = blockIdx.x * 4;
    const int lane = threadIdx.x & 31;
    const int warp = threadIdx.x >> 5;

    float acc[4][10];
#pragma unroll
    for (int bb = 0; bb < 4; bb++)
#pragma unroll
        for (int o = 0; o < 10; o++) acc[bb][o] = 0.f;

    const int NF = 96 * GV;
    for (int f = threadIdx.x; f < NF; f += 256) {
        int c = f >> 10, v = f & (GV - 1);
        float sc = g_bn_s[c], sh = g_bn_t[c];
        float w[10];
#pragma unroll
        for (int o = 0; o < 10; o++) w[o] = cw[(size_t)o * NF + f];
#pragma unroll
        for (int bb = 0; bb < 4; bb++) {
            float y = g_act[(size_t)c * NN + (size_t)(b0 + bb) * GV + v];
            float h = fmaxf(fmaf(y, sc, sh), 0.f);
#pragma unroll
            for (int o = 0; o < 10; o++) acc[bb][o] = fmaf(h, w[o], acc[bb][o]);
        }
    }

    __shared__ float part[8][40];
#pragma unroll
    for (int bb = 0; bb < 4; bb++)
#pragma unroll
        for (int o = 0; o < 10; o++) {
            float vsum = acc[bb][o];
#pragma unroll
            for (int off = 16; off > 0; off >>= 1)
                vsum += __shfl_down_sync(0xffffffffu, vsum, off);
            if (lane == 0) part[warp][bb * 10 + o] = vsum;
        }
    __syncthreads();
    if (threadIdx.x < 40) {
        float ssum = 0.f;
#pragma unroll
        for (int wq = 0; wq < 8; wq++) ssum += part[wq][threadIdx.x];
        int bb = threadIdx.x / 10, o = threadIdx.x % 10;
        out[(b0 + bb) * 10 + o] = ssum + cb[o];
    }
}

// ---------------- launch ----------------
extern "C" void kernel_launch(void* const* d_in, const int* in_sizes, int n_in,
                              void* d_out, int out_size) {
    (void)out_size;
    const float* x = (const float*)d_in[0];
    const float* w[7];
    const float* gg[7];
    const float* bb[7];

    if (n_in >= 25 && in_sizes[3] == 96) {  // dict order (w,g,b per layer)
        for (int i = 0; i < 7; i++) {
            w[i]  = (const float*)d_in[2 + 3 * i];
            gg[i] = (const float*)d_in[3 + 3 * i];
            bb[i] = (const float*)d_in[4 + 3 * i];
        }
    } else {                                // signature order
        for (int i = 0; i < 7; i++) {
            w[i]  = (const float*)d_in[2 + i];
            gg[i] = (const float*)d_in[9 + i];
            bb[i] = (const float*)d_in[16 + i];
        }
    }
    const float* clf_w = (const float*)d_in[23];
    const float* clf_b = (const float*)d_in[24];

    static int smem_set = 0;
    if (!smem_set) {
        cudaFuncSetAttribute(gemm_mma, cudaFuncAttributeMaxDynamicSharedMemorySize, SMEM_GEMM);
        smem_set = 1;
    }

    const int CIN[7]  = {3, 96, 96, 96, 192, 192, 192};
    const int FOUT[7] = {96, 96, 96, 192, 192, 192, 96};

    for (int l = 0; l < 7; l++) {
        const int C = CIN[l], F = FOUT[l], CK = C * KORD;

        wsplit<<<(F * CKP + 255) / 256, 256>>>(w[l], F, CK);
        cheb_expand<<<dim3(C, GB), GV>>>(x, C, l == 0 ? 1 : 0);

        dim3 grid(F / 96, NN / 128);
        gemm_mma<<<grid, 256, SMEM_GEMM>>>(F, CK);

        bn_stats<<<F, 512>>>(gg[l], bb[l]);
    }

    classifier<<<32, 256>>>(clf_w, clf_b, (float*)d_out);
}

// round 7
// speedup vs baseline: 3.3036x; 1.6709x over previous
#include <cuda_runtime.h>
#include <cuda_bf16.h>
#include <cstdint>

#define GV 1024
#define GB 128
#define NN (GB * GV)          // 131072 columns (channel-major)
#define KORD 5
#define CKP 960               // padded K stride for split weights

// ---------------- scratch (device globals; no allocation) ----------------
__device__ __nv_bfloat16 g_fkh[(size_t)960 * NN];  // Fk hi plane [CK][NN]
__device__ __nv_bfloat16 g_fkl[(size_t)960 * NN];  // Fk lo plane [CK][NN]
__device__ float g_act[(size_t)192 * NN];          // conv output Y [F][NN] fp32
__device__ float g_bn_s[192];
__device__ float g_bn_t[192];
__device__ double g_dsum[192];
__device__ double g_dsq[192];
__device__ __nv_bfloat16 g_wh[192 * CKP];          // W hi plane [F][960]
__device__ __nv_bfloat16 g_wl[192 * CKP];          // W lo plane [F][960]

// ---------------- helpers ----------------
__device__ __forceinline__ uint32_t smem_u32(const void* p) {
    uint32_t a;
    asm("{ .reg .u64 t; cvta.to.shared.u64 t, %1; cvt.u32.u64 %0, t; }" : "=r"(a) : "l"(p));
    return a;
}

__device__ __forceinline__ void mma_bf16(float* d, const uint32_t* a, const uint32_t* b) {
    asm volatile(
        "mma.sync.aligned.m16n8k16.row.col.f32.bf16.bf16.f32 "
        "{%0,%1,%2,%3}, {%4,%5,%6,%7}, {%8,%9}, {%0,%1,%2,%3};"
        : "+f"(d[0]), "+f"(d[1]), "+f"(d[2]), "+f"(d[3])
        : "r"(a[0]), "r"(a[1]), "r"(a[2]), "r"(a[3]), "r"(b[0]), "r"(b[1]));
}

#define LDSM_X4(r0, r1, r2, r3, addr) \
    asm volatile("ldmatrix.sync.aligned.m8n8.x4.shared.b16 {%0,%1,%2,%3}, [%4];" \
                 : "=r"(r0), "=r"(r1), "=r"(r2), "=r"(r3) : "r"(addr))
#define LDSM_X4T(r0, r1, r2, r3, addr) \
    asm volatile("ldmatrix.sync.aligned.m8n8.x4.trans.shared.b16 {%0,%1,%2,%3}, [%4];" \
                 : "=r"(r0), "=r"(r1), "=r"(r2), "=r"(r3) : "r"(addr))

#define CP_ASYNC16(dst, src) \
    asm volatile("cp.async.ca.shared.global [%0], [%1], 16;" :: "r"(dst), "l"(src) : "memory")
#define CP_COMMIT() asm volatile("cp.async.commit_group;" ::: "memory")
#define CP_WAIT0()  asm volatile("cp.async.wait_group 0;" ::: "memory")

// ---------------- W split + accumulator zeroing ----------------
__global__ void wsplit(const float* __restrict__ W, int F, int CK) {
    int idx = blockIdx.x * 256 + threadIdx.x;
    if (blockIdx.x == 0 && threadIdx.x < 192) {
        g_dsum[threadIdx.x] = 0.0;
        g_dsq[threadIdx.x]  = 0.0;
    }
    if (idx >= F * CKP) return;
    int k = idx % CKP;
    int f = idx / CKP;
    float v = (k < CK) ? W[(size_t)f * CK + k] : 0.f;
    __nv_bfloat16 h = __float2bfloat16_rn(v);
    g_wh[idx] = h;
    g_wl[idx] = __float2bfloat16_rn(v - __bfloat162float(h));
}

// ---------------- Chebyshev expansion, writes bf16 hi/lo planes ----------------
__device__ __forceinline__ float rsd_of(int i, int j) {
    int deg = (i > 0) + (i < 31) + (j > 0) + (j < 31);
    return (deg == 4) ? 0.5f : (deg == 3 ? 0.57735026918962576f : 0.70710678118654752f);
}

__device__ __forceinline__ void store_split(size_t idx, float x) {
    __nv_bfloat16 h = __float2bfloat16_rn(x);
    g_fkh[idx] = h;
    g_fkl[idx] = __float2bfloat16_rn(x - __bfloat162float(h));
}

__global__ void cheb_expand(const float* __restrict__ xin, int C, int layer0) {
    __shared__ float s[GV];
    const int v = threadIdx.x;
    const int c = blockIdx.x;
    const int b = blockIdx.y;
    const int i = v >> 5, j = v & 31;

    float x;
    if (layer0) {
        x = xin[((size_t)b * C + c) * GV + v];
    } else {
        x = g_act[(size_t)c * NN + (size_t)b * GV + v];
        x = fmaxf(fmaf(x, g_bn_s[c], g_bn_t[c]), 0.0f);
    }

    const float rv = rsd_of(i, j);
    const float w_up = (i > 0)  ? rv * rsd_of(i - 1, j) : 0.f;
    const float w_dn = (i < 31) ? rv * rsd_of(i + 1, j) : 0.f;
    const float w_lf = (j > 0)  ? rv * rsd_of(i, j - 1) : 0.f;
    const float w_rt = (j < 31) ? rv * rsd_of(i, j + 1) : 0.f;
    const int up = (i > 0)  ? v - 32 : v;
    const int dn = (i < 31) ? v + 32 : v;
    const int lf = (j > 0)  ? v - 1  : v;
    const int rt = (j < 31) ? v + 1  : v;

    const size_t base = (size_t)(c * KORD) * NN + (size_t)b * GV + v;

    store_split(base, x);
    s[v] = x;
    __syncthreads();
    float t1 = -(w_up * s[up] + w_dn * s[dn] + w_lf * s[lf] + w_rt * s[rt]);
    store_split(base + NN, t1);

    float tp = x, tc = t1;
#pragma unroll
    for (int k = 2; k < KORD; k++) {
        __syncthreads();
        s[v] = tc;
        __syncthreads();
        float l = -(w_up * s[up] + w_dn * s[dn] + w_lf * s[lf] + w_rt * s[rt]);
        float tn = fmaf(2.0f, l, -tp);
        store_split(base + (size_t)k * NN, tn);
        tp = tc;
        tc = tn;
    }
}

// ---------------- tensor-core GEMM (mma.sync bf16 hi/lo 3-term) + fused BN stats ----
// CTA: 96m x 128n, BK=32. 8 warps = 2(m) x 4(n); warp tile 48m x 32n.
// smem/stage: Ah[96][80B] Al[96][80B] Bh[32][272B] Bl[32][272B] = 32768 B
#define ROWA 80
#define ROWBB 272
#define SZ_AP (96 * ROWA)                 // 7680
#define SZ_BP (32 * ROWBB)                // 8704
#define OFF_AH 0
#define OFF_AL SZ_AP
#define OFF_BH (2 * SZ_AP)
#define OFF_BL (2 * SZ_AP + SZ_BP)
#define STAGE  (2 * SZ_AP + 2 * SZ_BP)    // 32768
#define SMEM_GEMM (2 * STAGE)             // 65536

__global__ void __launch_bounds__(256, 2)
gemm_mma(int F, int CK) {
    extern __shared__ char smem[];
    const uint32_t sbase = smem_u32(smem);

    const int tid  = threadIdx.x;
    const int lane = tid & 31;
    const int wid  = tid >> 5;
    const int wm   = wid & 1;        // 0..1  (m)
    const int wn   = wid >> 1;       // 0..3  (n)
    const int g    = lane >> 2;      // 0..7
    const int t4   = lane & 3;       // 0..3
    const int l15  = lane & 15;
    const int lhi  = lane >> 4;      // 0..1

    const int m0 = blockIdx.x * 96;
    const int n0 = blockIdx.y * 128;
    const int ns = (CK + 31) >> 5;

    float acc[3][4][4];
#pragma unroll
    for (int a = 0; a < 3; a++)
#pragma unroll
        for (int b = 0; b < 4; b++)
#pragma unroll
            for (int c = 0; c < 4; c++) acc[a][b][c] = 0.f;

    // ---- async load of one stage (A: 768 chunks, B: 1024 chunks) ----
    auto load_stage = [&](uint32_t sdst, int k0) {
#pragma unroll
        for (int i = 0; i < 3; i++) {              // A planes
            int e = tid + 256 * i;
            int p = e >= 384;
            int id = e - 384 * p;
            int r = id >> 2, q = id & 3;
            const __nv_bfloat16* src = (p ? g_wl : g_wh) + (size_t)(m0 + r) * CKP + k0 + q * 8;
            CP_ASYNC16(sdst + (p ? OFF_AL : OFF_AH) + r * ROWA + q * 16, src);
        }
#pragma unroll
        for (int i = 0; i < 4; i++) {              // B planes
            int e = tid + 256 * i;
            int p = e >= 512;
            int id = e - 512 * p;
            int k = id >> 4, cc = id & 15;
            const __nv_bfloat16* src = (p ? g_fkl : g_fkh) + (size_t)(k0 + k) * NN + n0 + cc * 8;
            CP_ASYNC16(sdst + (p ? OFF_BL : OFF_BH) + k * ROWBB + cc * 16, src);
        }
        CP_COMMIT();
    };

    load_stage(sbase, 0);
    CP_WAIT0();
    __syncthreads();

    for (int s = 0; s < ns; s++) {
        const uint32_t buf = sbase + (uint32_t)(s & 1) * STAGE;
        const bool more = (s + 1 < ns);
        if (more) load_stage(sbase + (uint32_t)((s + 1) & 1) * STAGE, (s + 1) * 32);

#pragma unroll
        for (int c = 0; c < 2; c++) {
            uint32_t ah[3][4], al[3][4];
#pragma unroll
            for (int mf = 0; mf < 3; mf++) {
                int row = wm * 48 + mf * 16 + l15;
                uint32_t qa = (uint32_t)(2 * c + lhi);
                uint32_t addr = buf + OFF_AH + row * ROWA + qa * 16;
                LDSM_X4(ah[mf][0], ah[mf][1], ah[mf][2], ah[mf][3], addr);
                LDSM_X4(al[mf][0], al[mf][1], al[mf][2], al[mf][3], addr + (OFF_AL - OFF_AH));
            }
            uint32_t bh[2][4], bl[2][4];
#pragma unroll
            for (int p = 0; p < 2; p++) {
                int krow = 16 * c + l15;
                int nbyte = wn * 64 + p * 32 + lhi * 16;
                uint32_t addr = buf + OFF_BH + krow * ROWBB + nbyte;
                LDSM_X4T(bh[p][0], bh[p][1], bh[p][2], bh[p][3], addr);
                LDSM_X4T(bl[p][0], bl[p][1], bl[p][2], bl[p][3], addr + (OFF_BL - OFF_BH));
            }
#pragma unroll
            for (int p = 0; p < 2; p++)
#pragma unroll
                for (int h = 0; h < 2; h++) {
                    int nf = 2 * p + h;
#pragma unroll
                    for (int mf = 0; mf < 3; mf++) {
                        mma_bf16(acc[mf][nf], ah[mf], &bh[p][2 * h]);
                        mma_bf16(acc[mf][nf], al[mf], &bh[p][2 * h]);
                        mma_bf16(acc[mf][nf], ah[mf], &bl[p][2 * h]);
                    }
                }
        }
        if (more) CP_WAIT0();
        __syncthreads();
    }

    // ---- epilogue 1: fragments -> g_act ----
#pragma unroll
    for (int mf = 0; mf < 3; mf++) {
        int mrow = m0 + wm * 48 + mf * 16 + g;
#pragma unroll
        for (int nf = 0; nf < 4; nf++) {
            int col = n0 + wn * 32 + nf * 8 + 2 * t4;
            *(float2*)(g_act + (size_t)mrow * NN + col) =
                make_float2(acc[mf][nf][0], acc[mf][nf][1]);
            *(float2*)(g_act + (size_t)(mrow + 8) * NN + col) =
                make_float2(acc[mf][nf][2], acc[mf][nf][3]);
        }
    }

    // ---- epilogue 2: fused BN partial stats (row sums over the 128-col tile) ----
    float* reds = (float*)smem;          // [96][4]
    float* redq = (float*)smem + 384;    // [96][4]
#pragma unroll
    for (int mf = 0; mf < 3; mf++) {
#pragma unroll
        for (int half = 0; half < 2; half++) {
            float s = 0.f, q = 0.f;
#pragma unroll
            for (int nf = 0; nf < 4; nf++) {
                float v0 = acc[mf][nf][2 * half];
                float v1 = acc[mf][nf][2 * half + 1];
                s += v0 + v1;
                q += v0 * v0 + v1 * v1;
            }
            s += __shfl_xor_sync(0xffffffffu, s, 1);
            s += __shfl_xor_sync(0xffffffffu, s, 2);
            q += __shfl_xor_sync(0xffffffffu, q, 1);
            q += __shfl_xor_sync(0xffffffffu, q, 2);
            if (t4 == 0) {
                int row = wm * 48 + mf * 16 + half * 8 + g;
                reds[row * 4 + wn] = s;
                redq[row * 4 + wn] = q;
            }
        }
    }
    __syncthreads();
    if (tid < 96) {
        float s = reds[tid * 4] + reds[tid * 4 + 1] + reds[tid * 4 + 2] + reds[tid * 4 + 3];
        float q = redq[tid * 4] + redq[tid * 4 + 1] + redq[tid * 4 + 2] + redq[tid * 4 + 3];
        atomicAdd(&g_dsum[m0 + tid], (double)s);
        atomicAdd(&g_dsq[m0 + tid],  (double)q);
    }
}

// ---------------- BN finalize ----------------
__global__ void bn_final(const float* __restrict__ gamma, const float* __restrict__ beta, int F) {
    int f = threadIdx.x;
    if (f >= F) return;
    double mean = g_dsum[f] / (double)NN;
    double var  = g_dsq[f] / (double)NN - mean * mean;
    float sc = gamma[f] * rsqrtf((float)var + 1e-5f);
    g_bn_s[f] = sc;
    g_bn_t[f] = beta[f] - (float)mean * sc;
}

// ---------------- classifier ----------------
__global__ void classifier(const float* __restrict__ cw, const float* __restrict__ cb,
                           float* __restrict__ out) {
    const int b0   = blockIdx.x * 4;
    const int lane = threadIdx.x & 31;
    const int warp = threadIdx.x >> 5;

    float acc[4][10];
#pragma unroll
    for (int bb = 0; bb < 4; bb++)
#pragma unroll
        for (int o = 0; o < 10; o++) acc[bb][o] = 0.f;

    const int NF = 96 * GV;
    for (int f = threadIdx.x; f < NF; f += 256) {
        int c = f >> 10, v = f & (GV - 1);
        float sc = g_bn_s[c], sh = g_bn_t[c];
        float w[10];
#pragma unroll
        for (int o = 0; o < 10; o++) w[o] = cw[(size_t)o * NF + f];
#pragma unroll
        for (int bb = 0; bb < 4; bb++) {
            float y = g_act[(size_t)c * NN + (size_t)(b0 + bb) * GV + v];
            float h = fmaxf(fmaf(y, sc, sh), 0.f);
#pragma unroll
            for (int o = 0; o < 10; o++) acc[bb][o] = fmaf(h, w[o], acc[bb][o]);
        }
    }

    __shared__ float part[8][40];
#pragma unroll
    for (int bb = 0; bb < 4; bb++)
#pragma unroll
        for (int o = 0; o < 10; o++) {
            float vsum = acc[bb][o];
#pragma unroll
            for (int off = 16; off > 0; off >>= 1)
                vsum += __shfl_down_sync(0xffffffffu, vsum, off);
            if (lane == 0) part[warp][bb * 10 + o] = vsum;
        }
    __syncthreads();
    if (threadIdx.x < 40) {
        float ssum = 0.f;
#pragma unroll
        for (int wq = 0; wq < 8; wq++) ssum += part[wq][threadIdx.x];
        int bb = threadIdx.x / 10, o = threadIdx.x % 10;
        out[(b0 + bb) * 10 + o] = ssum + cb[o];
    }
}

// ---------------- launch ----------------
extern "C" void kernel_launch(void* const* d_in, const int* in_sizes, int n_in,
                              void* d_out, int out_size) {
    (void)out_size;
    const float* x = (const float*)d_in[0];
    const float* w[7];
    const float* gg[7];
    const float* bb[7];

    if (n_in >= 25 && in_sizes[3] == 96) {  // dict order (w,g,b per layer)
        for (int i = 0; i < 7; i++) {
            w[i]  = (const float*)d_in[2 + 3 * i];
            gg[i] = (const float*)d_in[3 + 3 * i];
            bb[i] = (const float*)d_in[4 + 3 * i];
        }
    } else {                                // signature order
        for (int i = 0; i < 7; i++) {
            w[i]  = (const float*)d_in[2 + i];
            gg[i] = (const float*)d_in[9 + i];
            bb[i] = (const float*)d_in[16 + i];
        }
    }
    const float* clf_w = (const float*)d_in[23];
    const float* clf_b = (const float*)d_in[24];

    static int smem_set = 0;
    if (!smem_set) {
        cudaFuncSetAttribute(gemm_mma, cudaFuncAttributeMaxDynamicSharedMemorySize, SMEM_GEMM);
        smem_set = 1;
    }

    const int CIN[7]  = {3, 96, 96, 96, 192, 192, 192};
    const int FOUT[7] = {96, 96, 96, 192, 192, 192, 96};

    for (int l = 0; l < 7; l++) {
        const int C = CIN[l], F = FOUT[l], CK = C * KORD;

        wsplit<<<(F * CKP + 255) / 256, 256>>>(w[l], F, CK);
        cheb_expand<<<dim3(C, GB), GV>>>(x, C, l == 0 ? 1 : 0);

        dim3 grid(F / 96, NN / 128);
        gemm_mma<<<grid, 256, SMEM_GEMM>>>(F, CK);

        bn_final<<<1, 192>>>(gg[l], bb[l], F);
    }

    classifier<<<32, 256>>>(clf_w, clf_b, (float*)d_out);
}